// round 1
// baseline (speedup 1.0000x reference)
#include <cuda_runtime.h>

// Input order (metadata): q, r, Ek, Ev, Mk, Mv0, We, be, Wa, ba, Wf, bf, Wp, bp
// q,r int32 [64,512]; the rest float32. Output: p [64,512] float32.

#define NUM_C 1000
#define DIM   128
#define MSZ   64
#define BB    64
#define LL    512
#define NTOK  (BB*LL)

typedef unsigned long long ull;

// ---------------- device scratch (static globals, no allocation) ----------------
__device__ float g_w   [NUM_C*MSZ];        // softmax(Ek[q] @ Mk^T)     [1000,64]
__device__ float g_e   [2*NUM_C*DIM];      // sigmoid(Ev@We+be)          [2000,128]
__device__ float g_a   [2*NUM_C*DIM];      // tanh(Ev@Wa+ba)             [2000,128]
__device__ float g_fk  [NUM_C*DIM];        // Ek@Wf[128:256] + bf        [1000,128]
__device__ float g_wseq[NTOK*MSZ];         // per-token w stream         [B*L,64]
__device__ float g_eseq[BB*2*LL*64];       // per-(batch,half) e stream
__device__ float g_aseq[BB*2*LL*64];       // per-(batch,half) a stream
__device__ float g_read[NTOK*DIM];         // scan output                [B*L,128]

// ---------------- f32x2 helpers ----------------
__device__ __forceinline__ ull fma2(ull a, ull b, ull c) {
    ull d;
    asm("fma.rn.f32x2 %0, %1, %2, %3;" : "=l"(d) : "l"(a), "l"(b), "l"(c));
    return d;
}
__device__ __forceinline__ ull add2(ull a, ull b) {
    ull d;
    asm("add.rn.f32x2 %0, %1, %2;" : "=l"(d) : "l"(a), "l"(b));
    return d;
}
__device__ __forceinline__ ull pack2(float x, float y) {
    ull d;
    asm("mov.b64 %0, {%1, %2};" : "=l"(d) : "f"(x), "f"(y));
    return d;
}
__device__ __forceinline__ float2 unpack2(ull v) {
    float2 r;
    asm("mov.b64 {%0, %1}, %2;" : "=f"(r.x), "=f"(r.y) : "l"(v));
    return r;
}
__device__ __forceinline__ float sigmoid_fast(float x) {
    return __fdividef(1.0f, 1.0f + __expf(-x));
}
__device__ __forceinline__ float tanh_fast(float x) {
    // saturates correctly for large |x| (expf overflow/underflow)
    return 1.0f - __fdividef(2.0f, __expf(2.0f * x) + 1.0f);
}

// ---------------- kernel 1: softmax correlation-weight table ----------------
__global__ void k_wtable(const float* __restrict__ Ek, const float* __restrict__ Mk) {
    __shared__ float ek[DIM];
    __shared__ float lg[MSZ];
    int qi = blockIdx.x, t = threadIdx.x;  // 64 threads, t = memory slot m
    ek[t]      = Ek[qi*DIM + t];
    ek[t + 64] = Ek[qi*DIM + 64 + t];
    __syncthreads();
    const float* mk = Mk + t*DIM;
    float a0 = 0.f, a1 = 0.f;
#pragma unroll 16
    for (int i = 0; i < DIM; i += 2) {
        a0 = fmaf(ek[i],   mk[i],   a0);
        a1 = fmaf(ek[i+1], mk[i+1], a1);
    }
    float lv = a0 + a1;
    lg[t] = lv;
    __syncthreads();
    float mx = -1e30f;
#pragma unroll 8
    for (int m = 0; m < MSZ; m++) mx = fmaxf(mx, lg[m]);
    float s = 0.f;
#pragma unroll 8
    for (int m = 0; m < MSZ; m++) s += __expf(lg[m] - mx);
    g_w[qi*MSZ + t] = __fdividef(__expf(lv - mx), s);
}

// ---------------- kernels 2-4: column-GEMM tables (W column in registers) ----------------
// MODE 0: sigmoid -> g_e ; MODE 1: tanh -> g_a ; MODE 2: identity -> g_fk
template <int MODE>
__global__ void __launch_bounds__(128) k_colgemm(const float* __restrict__ W,
                                                 const float* __restrict__ rows,
                                                 int nrows,
                                                 const float* __restrict__ bias) {
    __shared__ __align__(16) float sv[2][DIM];
    int t = threadIdx.x;
    float wreg[DIM];
#pragma unroll
    for (int i = 0; i < DIM; i++) wreg[i] = W[i*DIM + t];
    float bv = bias[t];
    float* outT = (MODE == 0) ? g_e : (MODE == 1) ? g_a : g_fk;
    int pb = 0;
    for (int row = blockIdx.x; row < nrows; row += gridDim.x) {
        sv[pb][t] = rows[row*DIM + t];
        __syncthreads();
        float a0 = bv, a1 = 0.f;
        const float4* s4 = (const float4*)sv[pb];
#pragma unroll
        for (int j = 0; j < DIM/4; j++) {
            float4 v = s4[j];
            a0 = fmaf(v.x, wreg[4*j+0], a0);
            a1 = fmaf(v.y, wreg[4*j+1], a1);
            a0 = fmaf(v.z, wreg[4*j+2], a0);
            a1 = fmaf(v.w, wreg[4*j+3], a1);
        }
        float g = a0 + a1;
        float o;
        if (MODE == 0)      o = sigmoid_fast(g);
        else if (MODE == 1) o = tanh_fast(g);
        else                o = g;
        outT[row*DIM + t] = o;
        pb ^= 1;
    }
}

// ---------------- kernel 5: gather tables into sequential streams ----------------
__global__ void k_gather(const int* __restrict__ q, const int* __restrict__ r) {
    int t = threadIdx.x;           // 128
    int base = blockIdx.x * 16;    // 2048 blocks * 16 tokens
    int h = t >> 6, c = t & 63;
#pragma unroll 4
    for (int it = 0; it < 16; it++) {
        int tok = base + it;
        int qv = q[tok];
        int xv = qv + NUM_C * r[tok];
        if (t < 64) g_wseq[tok*64 + t] = g_w[qv*MSZ + t];
        int b = tok >> 9, l = tok & 511;
        int di = ((b*2 + h)*LL + l)*64 + c;
        g_eseq[di] = g_e[xv*DIM + t];
        g_aseq[di] = g_a[xv*DIM + t];
    }
}

// ---------------- kernel 6: the sequential scan ----------------
// grid 128 = (batch, column-half); block 128 = 4 m-groups x 32 column-pairs.
// Thread holds Mv[16 slots][2 cols] as f32x2. 3 FFMA2 per slot per step.
struct SD { float w[16]; ull e2, a2; };

__device__ __forceinline__ void sd_load(SD& s, const float* wb, const float* eb,
                                        const float* ab, int l) {
    int lc = (l < LL) ? l : (LL - 1);
    const float4* wp = (const float4*)(wb + lc*64);
    float4 w0 = wp[0], w1 = wp[1], w2 = wp[2], w3 = wp[3];
    s.w[0]=w0.x; s.w[1]=w0.y; s.w[2]=w0.z; s.w[3]=w0.w;
    s.w[4]=w1.x; s.w[5]=w1.y; s.w[6]=w1.z; s.w[7]=w1.w;
    s.w[8]=w2.x; s.w[9]=w2.y; s.w[10]=w2.z; s.w[11]=w2.w;
    s.w[12]=w3.x; s.w[13]=w3.y; s.w[14]=w3.z; s.w[15]=w3.w;
    s.e2 = *(const ull*)(eb + lc*64);
    s.a2 = *(const ull*)(ab + lc*64);
}

template <int OW>
__device__ __forceinline__ void scan_step(const SD& s, ull mv[16], int l, int mg, int cp,
                                          ull (&sp)[2][4][32], float* rbase) {
    ull ne2 = s.e2 ^ 0x8000000080000000ULL;  // -e (packed)
    ull r0 = 0ULL, r1 = 0ULL;
#pragma unroll
    for (int j = 0; j < 16; j++) {
        ull w2 = pack2(s.w[j], s.w[j]);
        ull tt = fma2(mv[j], ne2, s.a2);              // t = a - mv*e
        if (j & 1) r1 = fma2(w2, mv[j], r1);          // read += w * mv_old
        else       r0 = fma2(w2, mv[j], r0);
        mv[j] = fma2(w2, tt, mv[j]);                  // mv += w * t
    }
    ull racc = add2(r0, r1);
    int pb = l & 1;
    if (mg != OW) sp[pb][mg][cp] = racc;
    __syncthreads();
    if (mg == OW) {
#pragma unroll
        for (int g = 0; g < 4; g++)
            if (g != OW) racc = add2(racc, sp[pb][g][cp]);
        *(ull*)(rbase + l*DIM) = racc;
    }
}

__global__ void __launch_bounds__(128, 1) k_scan(const float* __restrict__ Mv0) {
    __shared__ ull sp[2][4][32];
    int bx = blockIdx.x, b = bx >> 1, h = bx & 1;
    int tid = threadIdx.x, mg = tid >> 5, cp = tid & 31;

    ull mv[16];
    const float* m0 = Mv0 + h*64 + cp*2;
#pragma unroll
    for (int j = 0; j < 16; j++)
        mv[j] = *(const ull*)(m0 + (mg*16 + j)*DIM);

    const float* wb = g_wseq + (b*LL)*64 + mg*16;
    const float* eb = g_eseq + ((b*2 + h)*LL)*64 + cp*2;
    const float* ab = g_aseq + ((b*2 + h)*LL)*64 + cp*2;
    float* rb = g_read + (b*LL)*DIM + h*64 + cp*2;

    SD A0, A1, B0, B1;
    sd_load(A0, wb, eb, ab, 0);
    sd_load(A1, wb, eb, ab, 1);
    sd_load(B0, wb, eb, ab, 2);
    sd_load(B1, wb, eb, ab, 3);

    for (int l = 0; l < LL; l += 4) {
        scan_step<0>(A0, mv, l+0, mg, cp, sp, rb);
        scan_step<1>(A1, mv, l+1, mg, cp, sp, rb);
        sd_load(A0, wb, eb, ab, l+4);
        sd_load(A1, wb, eb, ab, l+5);
        scan_step<2>(B0, mv, l+2, mg, cp, sp, rb);
        scan_step<3>(B1, mv, l+3, mg, cp, sp, rb);
        sd_load(B0, wb, eb, ab, l+6);
        sd_load(B1, wb, eb, ab, l+7);
    }
}

// ---------------- kernel 7: f = tanh(read@Wf_r + fk), p = sigmoid(f.Wp + bp) ----------------
// block 128 = 2 i-halves x 64 d-pairs. Wf half-column-pair in 64 f32x2 regs (128 regs).
__global__ void __launch_bounds__(128, 2) k_fp(const int* __restrict__ q,
                                               const float* __restrict__ Wf,
                                               const float* __restrict__ Wp,
                                               const float* __restrict__ bp,
                                               float* __restrict__ out) {
    __shared__ __align__(16) ull rr[2][DIM];
    __shared__ ull part[2][64];
    __shared__ float red[2][2];
    int tid = threadIdx.x;
    int g = tid >> 6, p = tid & 63;

    ull wf[64];
#pragma unroll
    for (int j = 0; j < 64; j++)
        wf[j] = *(const ull*)(Wf + (g*64 + j)*DIM + 2*p);

    float wpx = Wp[2*p], wpy = Wp[2*p + 1];
    float bpv = bp[0];

    int pb = 0;
    for (int tok = blockIdx.x; tok < NTOK; tok += gridDim.x) {
        float rv = g_read[tok*DIM + tid];
        rr[pb][tid] = pack2(rv, rv);
        int qv = q[tok];
        ull acc0 = (g == 0) ? *(const ull*)(g_fk + qv*DIM + 2*p) : 0ULL;
        ull acc1 = 0ULL;
        __syncthreads();

        const ulonglong2* rp = (const ulonglong2*)&rr[pb][g*64];
#pragma unroll
        for (int j = 0; j < 32; j++) {
            ulonglong2 v = rp[j];
            acc0 = fma2(wf[2*j],     v.x, acc0);
            acc1 = fma2(wf[2*j + 1], v.y, acc1);
        }
        ull acc = add2(acc0, acc1);

        if (g == 1) part[pb][p] = acc;
        __syncthreads();
        if (g == 0) {
            acc = add2(acc, part[pb][p]);
            float2 f = unpack2(acc);
            float fx = tanh_fast(f.x), fy = tanh_fast(f.y);
            float pv = fmaf(fx, wpx, fy * wpy);
#pragma unroll
            for (int o = 16; o > 0; o >>= 1)
                pv += __shfl_xor_sync(0xffffffffu, pv, o);
            if ((tid & 31) == 0) red[pb][tid >> 5] = pv;
        }
        __syncthreads();
        if (tid == 0) out[tok] = sigmoid_fast(red[pb][0] + red[pb][1] + bpv);
        pb ^= 1;
    }
}

// ---------------- launch ----------------
extern "C" void kernel_launch(void* const* d_in, const int* in_sizes, int n_in,
                              void* d_out, int out_size) {
    const int*   q   = (const int*)d_in[0];
    const int*   r   = (const int*)d_in[1];
    const float* Ek  = (const float*)d_in[2];
    const float* Ev  = (const float*)d_in[3];
    const float* Mk  = (const float*)d_in[4];
    const float* Mv0 = (const float*)d_in[5];
    const float* We  = (const float*)d_in[6];
    const float* be  = (const float*)d_in[7];
    const float* Wa  = (const float*)d_in[8];
    const float* ba  = (const float*)d_in[9];
    const float* Wf  = (const float*)d_in[10];
    const float* bf  = (const float*)d_in[11];
    const float* Wp  = (const float*)d_in[12];
    const float* bp  = (const float*)d_in[13];
    float* out = (float*)d_out;

    k_wtable<<<NUM_C, 64>>>(Ek, Mk);
    k_colgemm<0><<<296, 128>>>(We, Ev, 2*NUM_C, be);
    k_colgemm<1><<<296, 128>>>(Wa, Ev, 2*NUM_C, ba);
    k_colgemm<2><<<296, 128>>>(Wf + DIM*DIM, Ek, NUM_C, bf);
    k_gather<<<NTOK/16, 128>>>(q, r);
    k_scan<<<2*BB, 128>>>(Mv0);
    k_fp<<<296, 128>>>(q, Wf, Wp, bp, out);
}

// round 2
// speedup vs baseline: 1.4320x; 1.4320x over previous
#include <cuda_runtime.h>

// Inputs: q, r, Ek, Ev, Mk, Mv0, We, be, Wa, ba, Wf, bf, Wp, bp
// q,r int32 [64,512]; rest float32. Output: p [64,512] float32.

#define NUM_C 1000
#define DIM   128
#define MSZ   64
#define BB    64
#define LL    512
#define NTOK  (BB*LL)

typedef unsigned long long ull;

// ---------------- device scratch ----------------
__device__ float g_w  [NUM_C*MSZ];     // softmax(Ek[q] @ Mk^T)          [1000,64]
__device__ float g_ne [2*NUM_C*DIM];   // -sigmoid(Ev@We+be)  (negated!) [2000,128]
__device__ float g_a  [2*NUM_C*DIM];   // tanh(Ev@Wa+ba)                 [2000,128]
__device__ float g_fk [NUM_C*DIM];     // Ek@Wf[128:256] + bf            [1000,128]
__device__ float g_read[NTOK*DIM];     // scan output                    [B*L,128]

// ---------------- f32x2 helpers ----------------
__device__ __forceinline__ ull fma2(ull a, ull b, ull c) {
    ull d; asm("fma.rn.f32x2 %0, %1, %2, %3;" : "=l"(d) : "l"(a), "l"(b), "l"(c)); return d;
}
__device__ __forceinline__ ull add2(ull a, ull b) {
    ull d; asm("add.rn.f32x2 %0, %1, %2;" : "=l"(d) : "l"(a), "l"(b)); return d;
}
__device__ __forceinline__ ull pack2(float x, float y) {
    ull d; asm("mov.b64 %0, {%1, %2};" : "=l"(d) : "f"(x), "f"(y)); return d;
}
__device__ __forceinline__ float2 unpack2(ull v) {
    float2 r; asm("mov.b64 {%0, %1}, %2;" : "=f"(r.x), "=f"(r.y) : "l"(v)); return r;
}
__device__ __forceinline__ float sigmoid_fast(float x) {
    return __fdividef(1.0f, 1.0f + __expf(-x));
}
__device__ __forceinline__ float tanh_fast(float x) {
    return 1.0f - __fdividef(2.0f, __expf(2.0f * x) + 1.0f);
}

// ======================================================================
// Kernel 1 (fused tables): blocks [0,500) wtable (2 q each);
// blocks [500,750) colgemm (20 rows each): 100 e, 100 a, 50 fk.
// ======================================================================
__global__ void __launch_bounds__(128) k_tables(
        const float* __restrict__ Ek, const float* __restrict__ Ev,
        const float* __restrict__ Mk,
        const float* __restrict__ We, const float* __restrict__ be,
        const float* __restrict__ Wa, const float* __restrict__ ba,
        const float* __restrict__ Wf, const float* __restrict__ bf) {
    int bid = blockIdx.x, t = threadIdx.x;
    if (bid < 500) {
        // ---- correlation-weight softmax table: q0 = 2*bid + h ----
        __shared__ float ek[2][DIM];
        __shared__ float lg[2][MSZ];
        int q0 = 2 * bid;
        ek[0][t] = Ek[q0*DIM + t];
        ek[1][t] = Ek[(q0+1)*DIM + t];
        __syncthreads();
        int h = t >> 6, m = t & 63;
        const float* mk  = Mk + m*DIM;
        const float* ekr = ek[h];
        float a0 = 0.f, a1 = 0.f;
#pragma unroll 16
        for (int i = 0; i < DIM; i += 2) {
            a0 = fmaf(ekr[i],   mk[i],   a0);
            a1 = fmaf(ekr[i+1], mk[i+1], a1);
        }
        float lv = a0 + a1;
        lg[h][m] = lv;
        __syncthreads();
        float mx = -1e30f;
#pragma unroll 8
        for (int j = 0; j < MSZ; j++) mx = fmaxf(mx, lg[h][j]);
        float s = 0.f;
#pragma unroll 8
        for (int j = 0; j < MSZ; j++) s += __expf(lg[h][j] - mx);
        g_w[(q0 + h)*MSZ + m] = __fdividef(__expf(lv - mx), s);
    } else {
        // ---- column GEMM tables, 20 rows per block ----
        int cb = bid - 500;
        const float *W, *bias, *rows;
        float* outp;
        int mode, row0;
        if (cb < 100)      { W = We;            bias = be; rows = Ev; outp = g_ne; mode = 0; row0 = cb*20; }
        else if (cb < 200) { W = Wa;            bias = ba; rows = Ev; outp = g_a;  mode = 1; row0 = (cb-100)*20; }
        else               { W = Wf + DIM*DIM;  bias = bf; rows = Ek; outp = g_fk; mode = 2; row0 = (cb-200)*20; }

        ull w2[64];
#pragma unroll
        for (int j = 0; j < 64; j++)
            w2[j] = pack2(W[(2*j)*DIM + t], W[(2*j+1)*DIM + t]);
        float bv = bias[t];

        __shared__ __align__(16) float sv[2][DIM];
        float nxt = rows[row0*DIM + t];
        int pb = 0;
        for (int i = 0; i < 20; i++) {
            sv[pb][t] = nxt;
            __syncthreads();
            if (i < 19) nxt = rows[(row0 + i + 1)*DIM + t];  // prefetch next row
            const ull* s2 = (const ull*)sv[pb];
            ull a0v = pack2(bv, 0.f), a1v = 0ULL;
#pragma unroll
            for (int j = 0; j < 64; j += 2) {
                a0v = fma2(s2[j],   w2[j],   a0v);
                a1v = fma2(s2[j+1], w2[j+1], a1v);
            }
            float2 fa = unpack2(add2(a0v, a1v));
            float gsum = fa.x + fa.y;
            float o;
            if (mode == 0)      o = -sigmoid_fast(gsum);   // store NEGATED erase
            else if (mode == 1) o = tanh_fast(gsum);
            else                o = gsum;
            outp[(row0 + i)*DIM + t] = o;
            pb ^= 1;
        }
    }
}

// ======================================================================
// Kernel 2: sequential scan, gather fused (loads straight from tables).
// grid 128 = (batch, column-half); block 128 = 4 m-groups x 32 col-pairs.
// ======================================================================
struct SD { float w[16]; ull ne2, a2; };

__device__ __forceinline__ void sd_load(SD& s, const int2* __restrict__ sidx,
                                        int l, int mg, int eoff) {
    int lc = (l < LL) ? l : (LL - 1);
    int2 ix = sidx[lc];
    const float4* wp = (const float4*)(g_w + ix.x + mg*16);
    float4 w0 = wp[0], w1 = wp[1], w2 = wp[2], w3 = wp[3];
    s.w[0]=w0.x; s.w[1]=w0.y; s.w[2]=w0.z; s.w[3]=w0.w;
    s.w[4]=w1.x; s.w[5]=w1.y; s.w[6]=w1.z; s.w[7]=w1.w;
    s.w[8]=w2.x; s.w[9]=w2.y; s.w[10]=w2.z; s.w[11]=w2.w;
    s.w[12]=w3.x; s.w[13]=w3.y; s.w[14]=w3.z; s.w[15]=w3.w;
    s.ne2 = *(const ull*)(g_ne + ix.y + eoff);
    s.a2  = *(const ull*)(g_a  + ix.y + eoff);
}

template <int OW>
__device__ __forceinline__ void scan_step(const SD& s, ull mv[16], int l, int mg, int cp,
                                          ull (&sp)[2][4][32], float* rbase) {
    ull r0 = 0ULL, r1 = 0ULL;
#pragma unroll
    for (int j = 0; j < 16; j++) {
        ull w2 = pack2(s.w[j], s.w[j]);           // free: dual-issues in fma gaps
        ull tt = fma2(mv[j], s.ne2, s.a2);        // t = a - mv*e   (ne = -e)
        if (j & 1) r1 = fma2(w2, mv[j], r1);      // read += w * mv_old
        else       r0 = fma2(w2, mv[j], r0);
        mv[j] = fma2(w2, tt, mv[j]);              // mv += w * t
    }
    ull racc = add2(r0, r1);
    int pb = l & 1;
    if (mg != OW) sp[pb][mg][cp] = racc;
    __syncthreads();
    if (mg == OW) {
#pragma unroll
        for (int g = 0; g < 4; g++)
            if (g != OW) racc = add2(racc, sp[pb][g][cp]);
        *(ull*)(rbase + l*DIM) = racc;
    }
}

__global__ void __launch_bounds__(128, 1) k_scan(const float* __restrict__ Mv0,
                                                 const int* __restrict__ q,
                                                 const int* __restrict__ r) {
    __shared__ ull sp[2][4][32];
    __shared__ int2 sidx[LL];
    int bx = blockIdx.x, b = bx >> 1, h = bx & 1;
    int tid = threadIdx.x, mg = tid >> 5, cp = tid & 31;

    for (int i = tid; i < LL; i += 128) {
        int qv = q[b*LL + i], rv = r[b*LL + i];
        sidx[i] = make_int2(qv*MSZ, (qv + NUM_C*rv)*DIM);
    }

    ull mv[16];
    const float* m0 = Mv0 + h*64 + cp*2;
#pragma unroll
    for (int j = 0; j < 16; j++)
        mv[j] = *(const ull*)(m0 + (mg*16 + j)*DIM);
    __syncthreads();

    int eoff = h*64 + cp*2;
    float* rb = g_read + (b*LL)*DIM + eoff;

    SD A0, A1, B0, B1;
    sd_load(A0, sidx, 0, mg, eoff);
    sd_load(A1, sidx, 1, mg, eoff);
    sd_load(B0, sidx, 2, mg, eoff);
    sd_load(B1, sidx, 3, mg, eoff);

    for (int l = 0; l < LL; l += 4) {
        scan_step<0>(A0, mv, l+0, mg, cp, sp, rb);
        scan_step<1>(A1, mv, l+1, mg, cp, sp, rb);
        sd_load(A0, sidx, l+4, mg, eoff);
        sd_load(A1, sidx, l+5, mg, eoff);
        scan_step<2>(B0, mv, l+2, mg, cp, sp, rb);
        scan_step<3>(B1, mv, l+3, mg, cp, sp, rb);
        sd_load(B0, sidx, l+6, mg, eoff);
        sd_load(B1, sidx, l+7, mg, eoff);
    }
}

// ======================================================================
// Kernel 3: f = tanh(read@Wf_r + fk), p = sigmoid(f.Wp + bp); 4 tokens/iter.
// block 128 = 2 input-halves x 64 output-pairs; Wf half-column-pair in regs.
// ======================================================================
__global__ void __launch_bounds__(128, 2) k_fp(const int* __restrict__ q,
                                               const float* __restrict__ Wf,
                                               const float* __restrict__ Wp,
                                               const float* __restrict__ bp,
                                               float* __restrict__ out) {
    __shared__ __align__(16) ull rr[4][DIM];
    __shared__ ull part[4][64];
    __shared__ float red[4][2];
    int tid = threadIdx.x;
    int g = tid >> 6, p = tid & 63;

    ull wf[64];
#pragma unroll
    for (int j = 0; j < 64; j++)
        wf[j] = *(const ull*)(Wf + (g*64 + j)*DIM + 2*p);
    float wpx = Wp[2*p], wpy = Wp[2*p + 1];
    float bpv = bp[0];

    for (int tok0 = blockIdx.x * 4; tok0 < NTOK; tok0 += gridDim.x * 4) {
        float rv[4];
#pragma unroll
        for (int tt = 0; tt < 4; tt++)
            rv[tt] = g_read[(tok0 + tt)*DIM + tid];
        ull fk0[4] = {0ULL, 0ULL, 0ULL, 0ULL};
        if (g == 0) {
#pragma unroll
            for (int tt = 0; tt < 4; tt++)
                fk0[tt] = *(const ull*)(g_fk + q[tok0 + tt]*DIM + 2*p);
        }
#pragma unroll
        for (int tt = 0; tt < 4; tt++)
            rr[tt][tid] = pack2(rv[tt], rv[tt]);
        __syncthreads();                               // A

        ull acc0[4], acc1[4];
#pragma unroll
        for (int tt = 0; tt < 4; tt++) { acc0[tt] = fk0[tt]; acc1[tt] = 0ULL; }
#pragma unroll
        for (int j = 0; j < 32; j++) {
#pragma unroll
            for (int tt = 0; tt < 4; tt++) {
                ulonglong2 v = ((const ulonglong2*)&rr[tt][g*64])[j];
                acc0[tt] = fma2(wf[2*j],     v.x, acc0[tt]);
                acc1[tt] = fma2(wf[2*j + 1], v.y, acc1[tt]);
            }
        }
        ull a4[4];
#pragma unroll
        for (int tt = 0; tt < 4; tt++) a4[tt] = add2(acc0[tt], acc1[tt]);

        if (g == 1) {
#pragma unroll
            for (int tt = 0; tt < 4; tt++) part[tt][p] = a4[tt];
        }
        __syncthreads();                               // B
        if (g == 0) {
            float pv[4];
#pragma unroll
            for (int tt = 0; tt < 4; tt++) {
                float2 f = unpack2(add2(a4[tt], part[tt][p]));
                pv[tt] = fmaf(tanh_fast(f.x), wpx, tanh_fast(f.y) * wpy);
            }
#pragma unroll
            for (int o = 16; o > 0; o >>= 1) {
#pragma unroll
                for (int tt = 0; tt < 4; tt++)
                    pv[tt] += __shfl_xor_sync(0xffffffffu, pv[tt], o);
            }
            if ((tid & 31) == 0) {
#pragma unroll
                for (int tt = 0; tt < 4; tt++) red[tt][tid >> 5] = pv[tt];
            }
        }
        __syncthreads();                               // C
        if (tid < 4)
            out[tok0 + tid] = sigmoid_fast(red[tid][0] + red[tid][1] + bpv);
    }
}

// ---------------- launch ----------------
extern "C" void kernel_launch(void* const* d_in, const int* in_sizes, int n_in,
                              void* d_out, int out_size) {
    const int*   q   = (const int*)d_in[0];
    const int*   r   = (const int*)d_in[1];
    const float* Ek  = (const float*)d_in[2];
    const float* Ev  = (const float*)d_in[3];
    const float* Mk  = (const float*)d_in[4];
    const float* Mv0 = (const float*)d_in[5];
    const float* We  = (const float*)d_in[6];
    const float* be  = (const float*)d_in[7];
    const float* Wa  = (const float*)d_in[8];
    const float* ba  = (const float*)d_in[9];
    const float* Wf  = (const float*)d_in[10];
    const float* bf  = (const float*)d_in[11];
    const float* Wp  = (const float*)d_in[12];
    const float* bp  = (const float*)d_in[13];
    float* out = (float*)d_out;

    k_tables<<<750, 128>>>(Ek, Ev, Mk, We, be, Wa, ba, Wf, bf);
    k_scan<<<2*BB, 128>>>(Mv0, q, r);
    k_fp<<<296, 128>>>(q, Wf, Wp, bp, out);
}

// round 3
// speedup vs baseline: 1.7944x; 1.2531x over previous
#include <cuda_runtime.h>

// Inputs: q, r, Ek, Ev, Mk, Mv0, We, be, Wa, ba, Wf, bf, Wp, bp
// q,r int32 [64,512]; rest float32. Output: p [64,512] float32.

#define NUM_C 1000
#define DIM   128
#define MSZ   64
#define BB    64
#define LL    512
#define NTOK  (BB*LL)

typedef unsigned long long ull;

// ---------------- device scratch ----------------
__device__ float g_w  [NUM_C*MSZ];     // softmax(Ek[q] @ Mk^T)          [1000,64]
__device__ float g_ne [2*NUM_C*DIM];   // -sigmoid(Ev@We+be)  (negated!) [2000,128]
__device__ float g_a  [2*NUM_C*DIM];   // tanh(Ev@Wa+ba)                 [2000,128]
__device__ float g_fk [NUM_C*DIM];     // Ek@Wf[128:256] + bf            [1000,128]
__device__ float g_read[NTOK*DIM];     // scan output                    [B*L,128]

// ---------------- f32x2 helpers ----------------
__device__ __forceinline__ ull fma2(ull a, ull b, ull c) {
    ull d; asm("fma.rn.f32x2 %0, %1, %2, %3;" : "=l"(d) : "l"(a), "l"(b), "l"(c)); return d;
}
__device__ __forceinline__ ull add2(ull a, ull b) {
    ull d; asm("add.rn.f32x2 %0, %1, %2;" : "=l"(d) : "l"(a), "l"(b)); return d;
}
__device__ __forceinline__ ull pack2(float x, float y) {
    ull d; asm("mov.b64 %0, {%1, %2};" : "=l"(d) : "f"(x), "f"(y)); return d;
}
__device__ __forceinline__ float2 unpack2(ull v) {
    float2 r; asm("mov.b64 {%0, %1}, %2;" : "=f"(r.x), "=f"(r.y) : "l"(v)); return r;
}
__device__ __forceinline__ float sigmoid_fast(float x) {
    return __fdividef(1.0f, 1.0f + __expf(-x));
}
__device__ __forceinline__ float tanh_fast(float x) {
    return 1.0f - __fdividef(2.0f, __expf(2.0f * x) + 1.0f);
}

// ======================================================================
// Kernel 1 (fused tables)
//   blocks [0,50):   wtable, 10 q-pairs each (Mk staged in padded shared,
//                    thread-private Mk row in f32x2 regs, ek broadcast)
//   blocks [50,300): colgemm, 20 rows each, 2 rows/iter w/ reg prefetch
// ======================================================================
#define WT_BLOCKS 50
#define WT_PAIRS  10

__global__ void __launch_bounds__(128) k_tables(
        const float* __restrict__ Ek, const float* __restrict__ Ev,
        const float* __restrict__ Mk,
        const float* __restrict__ We, const float* __restrict__ be,
        const float* __restrict__ Wa, const float* __restrict__ ba,
        const float* __restrict__ Wf, const float* __restrict__ bf) {
    __shared__ union {
        struct {
            float mk[MSZ][DIM + 2];     // padded: 2-way LDS conflicts only
            float ek[2][2][DIM];
            float xmax[2][4];
            float xsum[2][4];
        } wt;
        struct {
            float sv[2][DIM];
        } cg;
    } sm;

    int bid = blockIdx.x, t = threadIdx.x;

    if (bid < WT_BLOCKS) {
        // ---------- softmax correlation-weight table ----------
        int h = t >> 6, m = t & 63;
        int lane = t & 31, wid = t >> 5;

        // stage Mk coalesced into padded shared
        for (int idx = t; idx < MSZ * DIM; idx += 128)
            sm.wt.mk[idx >> 7][idx & 127] = Mk[idx];
        __syncthreads();

        // thread-private Mk row (f32x2), 2-way bank conflict max
        ull mk2[64];
#pragma unroll
        for (int j = 0; j < 64; j++)
            mk2[j] = pack2(sm.wt.mk[m][2*j], sm.wt.mk[m][2*j + 1]);

        int qp0 = bid * WT_PAIRS;
        float e0 = Ek[(2*qp0)*DIM + t];
        float e1 = Ek[(2*qp0 + 1)*DIM + t];
        int pb = 0;
        for (int i = 0; i < WT_PAIRS; i++) {
            sm.wt.ek[pb][0][t] = e0;
            sm.wt.ek[pb][1][t] = e1;
            __syncthreads();
            if (i + 1 < WT_PAIRS) {
                e0 = Ek[(2*(qp0 + i + 1))*DIM + t];
                e1 = Ek[(2*(qp0 + i + 1) + 1)*DIM + t];
            }
            // dot: ek broadcast from shared (warp-uniform h)
            const ull* ep = (const ull*)sm.wt.ek[pb][h];
            ull a0 = 0ULL, a1 = 0ULL;
#pragma unroll
            for (int j = 0; j < 64; j += 2) {
                a0 = fma2(ep[j],   mk2[j],   a0);
                a1 = fma2(ep[j+1], mk2[j+1], a1);
            }
            float2 ac = unpack2(add2(a0, a1));
            float lv = ac.x + ac.y;

            // softmax over 64 m (warps {0,1}=h0, {2,3}=h1)
            float wm = lv;
#pragma unroll
            for (int o = 16; o > 0; o >>= 1)
                wm = fmaxf(wm, __shfl_xor_sync(0xffffffffu, wm, o));
            if (lane == 0) sm.wt.xmax[pb][wid] = wm;
            __syncthreads();
            float mx = fmaxf(sm.wt.xmax[pb][h*2], sm.wt.xmax[pb][h*2 + 1]);
            float ev = __expf(lv - mx);
            float ws = ev;
#pragma unroll
            for (int o = 16; o > 0; o >>= 1)
                ws += __shfl_xor_sync(0xffffffffu, ws, o);
            if (lane == 0) sm.wt.xsum[pb][wid] = ws;
            __syncthreads();
            float s = sm.wt.xsum[pb][h*2] + sm.wt.xsum[pb][h*2 + 1];
            g_w[(2*(qp0 + i) + h)*MSZ + m] = __fdividef(ev, s);
            pb ^= 1;
        }
    } else {
        // ---------- column GEMM tables, 20 rows/block, 2 rows/iter ----------
        int cb = bid - WT_BLOCKS;
        const float *W, *bias, *rows;
        float* outp;
        int mode, row0;
        if (cb < 100)      { W = We;           bias = be; rows = Ev; outp = g_ne; mode = 0; row0 = cb*20; }
        else if (cb < 200) { W = Wa;           bias = ba; rows = Ev; outp = g_a;  mode = 1; row0 = (cb-100)*20; }
        else               { W = Wf + DIM*DIM; bias = bf; rows = Ek; outp = g_fk; mode = 2; row0 = (cb-200)*20; }

        ull w2[64];
#pragma unroll
        for (int j = 0; j < 64; j++)
            w2[j] = pack2(W[(2*j)*DIM + t], W[(2*j+1)*DIM + t]);
        float bv = bias[t];

        float nA = rows[row0*DIM + t];
        float nB = rows[(row0 + 1)*DIM + t];
        for (int i = 0; i < 10; i++) {
            sm.cg.sv[0][t] = nA;
            sm.cg.sv[1][t] = nB;
            __syncthreads();
            if (i < 9) {
                nA = rows[(row0 + 2*i + 2)*DIM + t];
                nB = rows[(row0 + 2*i + 3)*DIM + t];
            }
            const ull* sa = (const ull*)sm.cg.sv[0];
            const ull* sb = (const ull*)sm.cg.sv[1];
            ull aA0 = pack2(bv, 0.f), aA1 = 0ULL;
            ull aB0 = pack2(bv, 0.f), aB1 = 0ULL;
#pragma unroll
            for (int j = 0; j < 64; j += 2) {
                aA0 = fma2(sa[j],   w2[j],   aA0);
                aA1 = fma2(sa[j+1], w2[j+1], aA1);
                aB0 = fma2(sb[j],   w2[j],   aB0);
                aB1 = fma2(sb[j+1], w2[j+1], aB1);
            }
            float2 fA = unpack2(add2(aA0, aA1));
            float2 fB = unpack2(add2(aB0, aB1));
            float gA = fA.x + fA.y, gB = fB.x + fB.y;
            float oA, oB;
            if (mode == 0)      { oA = -sigmoid_fast(gA); oB = -sigmoid_fast(gB); }
            else if (mode == 1) { oA = tanh_fast(gA);     oB = tanh_fast(gB); }
            else                { oA = gA;                oB = gB; }
            outp[(row0 + 2*i)*DIM + t]     = oA;
            outp[(row0 + 2*i + 1)*DIM + t] = oB;
            __syncthreads();
        }
    }
}

// ======================================================================
// Kernel 2: sequential scan (gather fused).
// grid 128 = (batch, column-half); block 128 = 4 m-groups x 32 col-pairs.
// ======================================================================
struct SD { float w[16]; ull ne2, a2; };

__device__ __forceinline__ void sd_load(SD& s, const int2* __restrict__ sidx,
                                        int l, int mg, int eoff) {
    int lc = (l < LL) ? l : (LL - 1);
    int2 ix = sidx[lc];
    const float4* wp = (const float4*)(g_w + ix.x + mg*16);
    float4 w0 = wp[0], w1 = wp[1], w2 = wp[2], w3 = wp[3];
    s.w[0]=w0.x; s.w[1]=w0.y; s.w[2]=w0.z; s.w[3]=w0.w;
    s.w[4]=w1.x; s.w[5]=w1.y; s.w[6]=w1.z; s.w[7]=w1.w;
    s.w[8]=w2.x; s.w[9]=w2.y; s.w[10]=w2.z; s.w[11]=w2.w;
    s.w[12]=w3.x; s.w[13]=w3.y; s.w[14]=w3.z; s.w[15]=w3.w;
    s.ne2 = *(const ull*)(g_ne + ix.y + eoff);
    s.a2  = *(const ull*)(g_a  + ix.y + eoff);
}

template <int OW>
__device__ __forceinline__ void scan_step(const SD& s, ull mv[16], int l, int mg, int cp,
                                          ull (&sp)[2][4][32], float* rbase) {
    ull r0 = 0ULL, r1 = 0ULL;
#pragma unroll
    for (int j = 0; j < 16; j++) {
        ull w2 = pack2(s.w[j], s.w[j]);
        ull tt = fma2(mv[j], s.ne2, s.a2);        // t = a - mv*e   (ne = -e)
        if (j & 1) r1 = fma2(w2, mv[j], r1);      // read += w * mv_old
        else       r0 = fma2(w2, mv[j], r0);
        mv[j] = fma2(w2, tt, mv[j]);              // mv += w * t
    }
    ull racc = add2(r0, r1);
    int pb = l & 1;
    if (mg != OW) sp[pb][mg][cp] = racc;
    __syncthreads();
    if (mg == OW) {
#pragma unroll
        for (int g = 0; g < 4; g++)
            if (g != OW) racc = add2(racc, sp[pb][g][cp]);
        *(ull*)(rbase + l*DIM) = racc;
    }
}

__global__ void __launch_bounds__(128, 1) k_scan(const float* __restrict__ Mv0,
                                                 const int* __restrict__ q,
                                                 const int* __restrict__ r) {
    __shared__ ull sp[2][4][32];
    __shared__ int2 sidx[LL];
    int bx = blockIdx.x, b = bx >> 1, h = bx & 1;
    int tid = threadIdx.x, mg = tid >> 5, cp = tid & 31;

    for (int i = tid; i < LL; i += 128) {
        int qv = q[b*LL + i], rv = r[b*LL + i];
        sidx[i] = make_int2(qv*MSZ, (qv + NUM_C*rv)*DIM);
    }

    ull mv[16];
    const float* m0 = Mv0 + h*64 + cp*2;
#pragma unroll
    for (int j = 0; j < 16; j++)
        mv[j] = *(const ull*)(m0 + (mg*16 + j)*DIM);
    __syncthreads();

    int eoff = h*64 + cp*2;
    float* rb = g_read + (b*LL)*DIM + eoff;

    SD A0, A1, B0, B1;
    sd_load(A0, sidx, 0, mg, eoff);
    sd_load(A1, sidx, 1, mg, eoff);
    sd_load(B0, sidx, 2, mg, eoff);
    sd_load(B1, sidx, 3, mg, eoff);

    for (int l = 0; l < LL; l += 4) {
        scan_step<0>(A0, mv, l+0, mg, cp, sp, rb);
        scan_step<1>(A1, mv, l+1, mg, cp, sp, rb);
        sd_load(A0, sidx, l+4, mg, eoff);
        sd_load(A1, sidx, l+5, mg, eoff);
        scan_step<2>(B0, mv, l+2, mg, cp, sp, rb);
        scan_step<3>(B1, mv, l+3, mg, cp, sp, rb);
        sd_load(B0, sidx, l+6, mg, eoff);
        sd_load(B1, sidx, l+7, mg, eoff);
    }
}

// ======================================================================
// Kernel 3: f = tanh(read@Wf_r + fk), p = sigmoid(f.Wp + bp); 4 tokens/iter.
// ======================================================================
__global__ void __launch_bounds__(128, 2) k_fp(const int* __restrict__ q,
                                               const float* __restrict__ Wf,
                                               const float* __restrict__ Wp,
                                               const float* __restrict__ bp,
                                               float* __restrict__ out) {
    __shared__ __align__(16) ull rr[4][DIM];
    __shared__ ull part[4][64];
    __shared__ float red[4][2];
    int tid = threadIdx.x;
    int g = tid >> 6, p = tid & 63;

    ull wf[64];
#pragma unroll
    for (int j = 0; j < 64; j++)
        wf[j] = *(const ull*)(Wf + (g*64 + j)*DIM + 2*p);
    float wpx = Wp[2*p], wpy = Wp[2*p + 1];
    float bpv = bp[0];

    for (int tok0 = blockIdx.x * 4; tok0 < NTOK; tok0 += gridDim.x * 4) {
        float rv[4];
#pragma unroll
        for (int tt = 0; tt < 4; tt++)
            rv[tt] = g_read[(tok0 + tt)*DIM + tid];
        ull fk0[4] = {0ULL, 0ULL, 0ULL, 0ULL};
        if (g == 0) {
#pragma unroll
            for (int tt = 0; tt < 4; tt++)
                fk0[tt] = *(const ull*)(g_fk + q[tok0 + tt]*DIM + 2*p);
        }
#pragma unroll
        for (int tt = 0; tt < 4; tt++)
            rr[tt][tid] = pack2(rv[tt], rv[tt]);
        __syncthreads();                               // A

        ull acc0[4], acc1[4];
#pragma unroll
        for (int tt = 0; tt < 4; tt++) { acc0[tt] = fk0[tt]; acc1[tt] = 0ULL; }
#pragma unroll
        for (int j = 0; j < 32; j++) {
#pragma unroll
            for (int tt = 0; tt < 4; tt++) {
                ulonglong2 v = ((const ulonglong2*)&rr[tt][g*64])[j];
                acc0[tt] = fma2(wf[2*j],     v.x, acc0[tt]);
                acc1[tt] = fma2(wf[2*j + 1], v.y, acc1[tt]);
            }
        }
        ull a4[4];
#pragma unroll
        for (int tt = 0; tt < 4; tt++) a4[tt] = add2(acc0[tt], acc1[tt]);

        if (g == 1) {
#pragma unroll
            for (int tt = 0; tt < 4; tt++) part[tt][p] = a4[tt];
        }
        __syncthreads();                               // B
        if (g == 0) {
            float pv[4];
#pragma unroll
            for (int tt = 0; tt < 4; tt++) {
                float2 f = unpack2(add2(a4[tt], part[tt][p]));
                pv[tt] = fmaf(tanh_fast(f.x), wpx, tanh_fast(f.y) * wpy);
            }
#pragma unroll
            for (int o = 16; o > 0; o >>= 1) {
#pragma unroll
                for (int tt = 0; tt < 4; tt++)
                    pv[tt] += __shfl_xor_sync(0xffffffffu, pv[tt], o);
            }
            if ((tid & 31) == 0) {
#pragma unroll
                for (int tt = 0; tt < 4; tt++) red[tt][tid >> 5] = pv[tt];
            }
        }
        __syncthreads();                               // C
        if (tid < 4)
            out[tok0 + tid] = sigmoid_fast(red[tid][0] + red[tid][1] + bpv);
    }
}

// ---------------- launch ----------------
extern "C" void kernel_launch(void* const* d_in, const int* in_sizes, int n_in,
                              void* d_out, int out_size) {
    const int*   q   = (const int*)d_in[0];
    const int*   r   = (const int*)d_in[1];
    const float* Ek  = (const float*)d_in[2];
    const float* Ev  = (const float*)d_in[3];
    const float* Mk  = (const float*)d_in[4];
    const float* Mv0 = (const float*)d_in[5];
    const float* We  = (const float*)d_in[6];
    const float* be  = (const float*)d_in[7];
    const float* Wa  = (const float*)d_in[8];
    const float* ba  = (const float*)d_in[9];
    const float* Wf  = (const float*)d_in[10];
    const float* bf  = (const float*)d_in[11];
    const float* Wp  = (const float*)d_in[12];
    const float* bp  = (const float*)d_in[13];
    float* out = (float*)d_out;

    k_tables<<<300, 128>>>(Ek, Ev, Mk, We, be, Wa, ba, Wf, bf);
    k_scan<<<2*BB, 128>>>(Mv0, q, r);
    k_fp<<<296, 128>>>(q, Wf, Wp, bp, out);
}